// round 1
// baseline (speedup 1.0000x reference)
#include <cuda_runtime.h>
#include <math.h>

// Problem constants (fixed by the reference: B=64, T=2048, D=U=128)
#define PB 64
#define PT 2048
#define PD 128
#define PU 128
#define NROWS (PB * PT)          // 131072 rows of the score GEMM
#define TCHUNKS 16               // context partial chunks over T (2048/128)
#define TCHUNK 128

// -------- device scratch (no allocations allowed) --------
__device__ float g_W[PD * PU];            // W1_w + W2_w, [d][u] row-major
__device__ float g_bias[PU];              // W1_b + W2_b
__device__ float g_V[PU];                 // V_w
__device__ float g_score[NROWS];          // raw scores s[b*T + t]
__device__ float g_max[PB];
__device__ float g_rcp[PB];               // 1 / sum(exp(s - max))
__device__ float g_partial[PB * TCHUNKS * PD];

// ================= K0: fold weights =================
__global__ void prep_kernel(const float* __restrict__ W1w, const float* __restrict__ W1b,
                            const float* __restrict__ W2w, const float* __restrict__ W2b,
                            const float* __restrict__ Vw) {
    int i = blockIdx.x * blockDim.x + threadIdx.x;
    if (i < PD * PU) g_W[i] = W1w[i] + W2w[i];
    if (i < PU) {
        g_bias[i] = W1b[i] + W2b[i];
        g_V[i] = Vw[i];              // V_b is softmax-invariant; dropped
    }
}

// ================= K1: score kernel =================
// s[row] = sum_u V[u] * tanh( sum_d x[row,d]*W[d,u] + bias[u] )
// W in smem (64KB). Each warp processes R=8 rows per iteration; each lane owns
// 4 consecutive u-columns (u = 4*lane .. 4*lane+3). x rows staged in smem and
// broadcast-read per d. FFMA-pipe bound: 512 FFMA/row/lane.
#define K1_WARPS 16
#define K1_THREADS (K1_WARPS * 32)
#define ROWS_PER_WARP 8
#define K1_GRID 148

__global__ void __launch_bounds__(K1_THREADS, 1)
score_kernel(const float* __restrict__ enc) {
    extern __shared__ float smem[];
    float* Ws = smem;                             // [128][128] floats, 64KB
    float* Xall = smem + PD * PU;                 // K1_WARPS * R * 128 floats, 64KB

    const int tid  = threadIdx.x;
    const int warp = tid >> 5;
    const int lane = tid & 31;

    // cooperative load of W into smem (vectorized)
    {
        const float4* src = (const float4*)g_W;
        float4* dst = (float4*)Ws;
        for (int i = tid; i < PD * PU / 4; i += K1_THREADS) dst[i] = src[i];
    }
    __syncthreads();

    const float4 bias4 = ((const float4*)g_bias)[lane];
    const float4 V4    = ((const float4*)g_V)[lane];
    const float4* Wf4  = (const float4*)Ws;
    float* Xw = Xall + warp * (ROWS_PER_WARP * PD);
    float4* Xw4 = (float4*)Xw;

    const int total_warps = K1_GRID * K1_WARPS;           // 2368
    const int warp_gid = blockIdx.x * K1_WARPS + warp;
    const long stride = (long)total_warps * ROWS_PER_WARP; // 18944

    for (long row0 = (long)warp_gid * ROWS_PER_WARP; row0 < NROWS; row0 += stride) {
        __syncwarp();
        // stage 8 rows of x: one float4 per lane per row (coalesced LDG.128)
        #pragma unroll
        for (int r = 0; r < ROWS_PER_WARP; r++) {
            Xw4[r * 32 + lane] = ((const float4*)(enc + (row0 + r) * PD))[lane];
        }
        __syncwarp();

        float acc[ROWS_PER_WARP][4];
        #pragma unroll
        for (int r = 0; r < ROWS_PER_WARP; r++) {
            acc[r][0] = bias4.x; acc[r][1] = bias4.y;
            acc[r][2] = bias4.z; acc[r][3] = bias4.w;
        }

        #pragma unroll 2
        for (int d = 0; d < PD; d++) {
            const float4 w = Wf4[d * 32 + lane];   // conflict-free: 512B row
            #pragma unroll
            for (int r = 0; r < ROWS_PER_WARP; r++) {
                const float xv = Xw[r * PD + d];   // smem broadcast
                acc[r][0] = fmaf(xv, w.x, acc[r][0]);
                acc[r][1] = fmaf(xv, w.y, acc[r][1]);
                acc[r][2] = fmaf(xv, w.z, acc[r][2]);
                acc[r][3] = fmaf(xv, w.w, acc[r][3]);
            }
        }

        // tanh + V-dot + warp reduce -> one score per row
        #pragma unroll
        for (int r = 0; r < ROWS_PER_WARP; r++) {
            float p = V4.x * tanhf(acc[r][0])
                    + V4.y * tanhf(acc[r][1])
                    + V4.z * tanhf(acc[r][2])
                    + V4.w * tanhf(acc[r][3]);
            #pragma unroll
            for (int o = 16; o > 0; o >>= 1) p += __shfl_xor_sync(0xFFFFFFFFu, p, o);
            if (lane == 0) g_score[row0 + r] = p;
        }
    }
}

// ================= K2: per-batch softmax stats =================
__global__ void softmax_stats_kernel() {
    const int b = blockIdx.x;
    const int tid = threadIdx.x;                 // 256 threads
    __shared__ float red[256];
    const float* s = g_score + b * PT;

    float m = -1e30f;
    for (int t = tid; t < PT; t += 256) m = fmaxf(m, s[t]);
    red[tid] = m;
    __syncthreads();
    for (int o = 128; o > 0; o >>= 1) {
        if (tid < o) red[tid] = fmaxf(red[tid], red[tid + o]);
        __syncthreads();
    }
    m = red[0];
    __syncthreads();

    float sum = 0.0f;
    for (int t = tid; t < PT; t += 256) sum += expf(s[t] - m);
    red[tid] = sum;
    __syncthreads();
    for (int o = 128; o > 0; o >>= 1) {
        if (tid < o) red[tid] += red[tid + o];
        __syncthreads();
    }
    if (tid == 0) {
        g_max[b] = m;
        g_rcp[b] = 1.0f / red[0];
    }
}

// ================= K3: partial contexts (deterministic, no atomics) =======
// grid (TCHUNKS, B), 128 threads (thread = d). Each block handles 128 t's.
__global__ void context_partial_kernel(const float* __restrict__ enc) {
    const int c = blockIdx.x;
    const int b = blockIdx.y;
    const int d = threadIdx.x;
    __shared__ float wgt[TCHUNK];

    const int t0 = c * TCHUNK;
    const float m = g_max[b];
    const float rcp = g_rcp[b];
    wgt[d] = expf(g_score[b * PT + t0 + d] - m) * rcp;
    __syncthreads();

    const float* x = enc + ((long)b * PT + t0) * PD + d;
    float a0 = 0.f, a1 = 0.f, a2 = 0.f, a3 = 0.f;
    #pragma unroll
    for (int t = 0; t < TCHUNK; t += 4) {
        a0 = fmaf(wgt[t + 0], x[(t + 0) * PD], a0);
        a1 = fmaf(wgt[t + 1], x[(t + 1) * PD], a1);
        a2 = fmaf(wgt[t + 2], x[(t + 2) * PD], a2);
        a3 = fmaf(wgt[t + 3], x[(t + 3) * PD], a3);
    }
    g_partial[(b * TCHUNKS + c) * PD + d] = (a0 + a1) + (a2 + a3);
}

// ================= K4: deterministic final reduce =================
__global__ void context_reduce_kernel(float* __restrict__ out) {
    const int b = blockIdx.x;
    const int d = threadIdx.x;
    float acc = 0.0f;
    #pragma unroll
    for (int c = 0; c < TCHUNKS; c++) acc += g_partial[(b * TCHUNKS + c) * PD + d];
    out[b * PD + d] = acc;
}

// ================= launch =================
extern "C" void kernel_launch(void* const* d_in, const int* in_sizes, int n_in,
                              void* d_out, int out_size) {
    const float* enc = (const float*)d_in[0];   // [64,2048,128]
    const float* W1w = (const float*)d_in[1];   // [128,128]
    const float* W1b = (const float*)d_in[2];   // [128]
    const float* W2w = (const float*)d_in[3];   // [128,128]
    const float* W2b = (const float*)d_in[4];   // [128]
    const float* Vw  = (const float*)d_in[5];   // [128,1]
    // d_in[6] = V_b: softmax-invariant, unused
    float* out = (float*)d_out;                 // [64,128] fp32

    const int k1_smem = (PD * PU + K1_WARPS * ROWS_PER_WARP * PD) * (int)sizeof(float); // 128KB
    cudaFuncSetAttribute(score_kernel, cudaFuncAttributeMaxDynamicSharedMemorySize, k1_smem);

    prep_kernel<<<64, 256>>>(W1w, W1b, W2w, W2b, Vw);
    score_kernel<<<K1_GRID, K1_THREADS, k1_smem>>>(enc);
    softmax_stats_kernel<<<PB, 256>>>();
    dim3 g3(TCHUNKS, PB);
    context_partial_kernel<<<g3, TCHUNK>>>(enc);
    context_reduce_kernel<<<PB, PD>>>(out);
}

// round 4
// speedup vs baseline: 2.0886x; 2.0886x over previous
#include <cuda_runtime.h>
#include <cuda_bf16.h>
#include <math.h>
#include <stdint.h>

// Problem constants: B=64, T=2048, D=U=128
#define PB 64
#define PT 2048
#define PD 128
#define PU 128
#define NROWS (PB * PT)           // 131072
#define NWTILES (NROWS / 16)      // 8192 warp-tiles of 16 rows
#define SGRID 148
#define K1_WARPS 8
#define K1_THREADS (K1_WARPS * 32)
#define TOTAL_WARPS (SGRID * K1_WARPS)   // 1184
#define TCHUNKS 16
#define TCHUNK 128

// W smem: 128 rows x (256B data + 16B pad) per matrix
#define WPITCH 272
#define WBYTES (PD * WPITCH)      // 34816
#define K1_DSMEM (2 * WBYTES)     // 69632 bytes dynamic smem

// ---------------- device scratch ----------------
__device__ __align__(16) __nv_bfloat16 g_W_hi[PD * PU];  // (W1+W2) hi, [d][u]
__device__ __align__(16) __nv_bfloat16 g_W_lo[PD * PU];  // residual lo, [d][u]
__device__ float g_bias[PU];
__device__ float g_V[PU];
__device__ float g_score[NROWS];
__device__ float g_max[PB];
__device__ float g_rcp[PB];
__device__ __align__(16) float g_partial[PB * TCHUNKS * PD];

// ---------------- helpers ----------------
__device__ __forceinline__ uint32_t smem_u32(const void* p) {
    uint32_t a;
    asm("{ .reg .u64 t; cvta.to.shared.u64 t, %1; cvt.u32.u64 %0, t; }" : "=r"(a) : "l"(p));
    return a;
}
__device__ __forceinline__ uint32_t pack_bf(float a, float b) {
    __nv_bfloat162 t = __floats2bfloat162_rn(a, b);
    return *reinterpret_cast<uint32_t*>(&t);
}
#define LDSM4T(r0, r1, r2, r3, addr) \
    asm volatile("ldmatrix.sync.aligned.m8n8.x4.trans.shared.b16 {%0,%1,%2,%3}, [%4];" \
                 : "=r"(r0), "=r"(r1), "=r"(r2), "=r"(r3) : "r"(addr))
#define MMA16816(d0, d1, d2, d3, a0, a1, a2, a3, b0, b1) \
    asm volatile("mma.sync.aligned.m16n8k16.row.col.f32.bf16.bf16.f32 " \
                 "{%0,%1,%2,%3}, {%4,%5,%6,%7}, {%8,%9}, {%0,%1,%2,%3};" \
                 : "+f"(d0), "+f"(d1), "+f"(d2), "+f"(d3) \
                 : "r"(a0), "r"(a1), "r"(a2), "r"(a3), "r"(b0), "r"(b1))

// ================= K0: fold + split weights (keeps [d][u] layout) =========
__global__ void prep_kernel(const float* __restrict__ W1w, const float* __restrict__ W1b,
                            const float* __restrict__ W2w, const float* __restrict__ W2b,
                            const float* __restrict__ Vw) {
    int i = blockIdx.x * blockDim.x + threadIdx.x;
    if (i < PD * PU) {
        float w = W1w[i] + W2w[i];
        __nv_bfloat16 hi = __float2bfloat16_rn(w);
        g_W_hi[i] = hi;
        g_W_lo[i] = __float2bfloat16_rn(w - __bfloat162float(hi));
    }
    if (i < PU) {
        g_bias[i] = W1b[i] + W2b[i];
        g_V[i] = Vw[i];               // V_b softmax-invariant, dropped
    }
}

// ================= K1: mma.sync score kernel =================
// s[row] = sum_u V[u] * tanh( (x @ W)[row,u] + bias[u] ), x@W via 3-term bf16 split.
// Warp-tile: 16 rows x 128 cols. A from gmem (register split), B (W) from smem
// via ldmatrix.x4.trans. acc: 16 n-chunks x 4 fp32 regs.
__global__ void __launch_bounds__(K1_THREADS, 1) score_kernel(const float* __restrict__ enc) {
    extern __shared__ __align__(16) char Wsm[];      // [0]=hi, [WBYTES]=lo (dynamic, 68KB)
    __shared__ float bias_s[PU], V_s[PU];

    const int tid = threadIdx.x, warp = tid >> 5, lane = tid & 31;
    const int g = lane >> 2, c = lane & 3;

    // stage W_hi/W_lo into padded smem (16B chunks)
    {
        const uint4* sh = (const uint4*)g_W_hi;
        const uint4* sl = (const uint4*)g_W_lo;
        for (int i = tid; i < PD * 16; i += K1_THREADS) {
            int row = i >> 4, ch = i & 15;
            *(uint4*)(Wsm + row * WPITCH + ch * 16) = sh[i];
            *(uint4*)(Wsm + WBYTES + row * WPITCH + ch * 16) = sl[i];
        }
        if (tid < PU) { bias_s[tid] = g_bias[tid]; V_s[tid] = g_V[tid]; }
    }
    __syncthreads();

    // per-lane ldmatrix base offset: mat0:(k+lr,n0) mat1:(k+8+lr,n0) mat2:(k+lr,n0+8) mat3:(k+8+lr,n0+8)
    const uint32_t lr = lane & 7, lg = lane >> 3;
    const uint32_t lds_off = (lr + ((lg & 1) << 3)) * WPITCH + ((lg >> 1) << 3) * 2;
    const uint32_t whi_a = smem_u32(Wsm) + lds_off;
    const uint32_t wlo_a = whi_a + WBYTES;

    const int gw = blockIdx.x * K1_WARPS + warp;

    for (int wt = gw; wt < NWTILES; wt += TOTAL_WARPS) {
        const long row0 = (long)wt * 16;
        const float* xr  = enc + (row0 + g) * PD + 2 * c;
        const float* xr8 = xr + 8 * PD;

        // init accumulators with bias (acc[np][0..1] and [2..3] share columns)
        float acc[16][4];
        #pragma unroll
        for (int np = 0; np < 16; np++) {
            float2 bb = *(const float2*)&bias_s[np * 8 + 2 * c];
            acc[np][0] = bb.x; acc[np][1] = bb.y;
            acc[np][2] = bb.x; acc[np][3] = bb.y;
        }

        #pragma unroll
        for (int k = 0; k < 8; k++) {
            // A fragment: load fp32, split to bf16 hi/lo in regs
            float2 p00 = *(const float2*)(xr  + k * 16);      // row g,   cols 2c..2c+1
            float2 p10 = *(const float2*)(xr8 + k * 16);      // row g+8
            float2 p01 = *(const float2*)(xr  + k * 16 + 8);  // row g,   cols 2c+8..
            float2 p11 = *(const float2*)(xr8 + k * 16 + 8);  // row g+8
            uint32_t Ah[4], Al[4];
            Ah[0] = pack_bf(p00.x, p00.y);
            Ah[1] = pack_bf(p10.x, p10.y);
            Ah[2] = pack_bf(p01.x, p01.y);
            Ah[3] = pack_bf(p11.x, p11.y);
            {
                __nv_bfloat162* h = (__nv_bfloat162*)Ah;
                float2 r0 = __bfloat1622float2(h[0]);
                float2 r1 = __bfloat1622float2(h[1]);
                float2 r2 = __bfloat1622float2(h[2]);
                float2 r3 = __bfloat1622float2(h[3]);
                Al[0] = pack_bf(p00.x - r0.x, p00.y - r0.y);
                Al[1] = pack_bf(p10.x - r1.x, p10.y - r1.y);
                Al[2] = pack_bf(p01.x - r2.x, p01.y - r2.y);
                Al[3] = pack_bf(p11.x - r3.x, p11.y - r3.y);
            }

            const uint32_t koff = (uint32_t)k * (16 * WPITCH);
            #pragma unroll
            for (int np2 = 0; np2 < 8; np2++) {
                uint32_t bh0, bh1, bh2, bh3, bl0, bl1, bl2, bl3;
                LDSM4T(bh0, bh1, bh2, bh3, whi_a + koff + np2 * 32);
                LDSM4T(bl0, bl1, bl2, bl3, wlo_a + koff + np2 * 32);
                float* a0 = acc[np2 * 2];
                float* a1 = acc[np2 * 2 + 1];
                MMA16816(a0[0], a0[1], a0[2], a0[3], Ah[0], Ah[1], Ah[2], Ah[3], bh0, bh1);
                MMA16816(a1[0], a1[1], a1[2], a1[3], Ah[0], Ah[1], Ah[2], Ah[3], bh2, bh3);
                MMA16816(a0[0], a0[1], a0[2], a0[3], Al[0], Al[1], Al[2], Al[3], bh0, bh1);
                MMA16816(a1[0], a1[1], a1[2], a1[3], Al[0], Al[1], Al[2], Al[3], bh2, bh3);
                MMA16816(a0[0], a0[1], a0[2], a0[3], Ah[0], Ah[1], Ah[2], Ah[3], bl0, bl1);
                MMA16816(a1[0], a1[1], a1[2], a1[3], Ah[0], Ah[1], Ah[2], Ah[3], bl2, bl3);
            }
        }

        // epilogue: tanh + V-dot, quad reduce, write 2 scores per quad-leader
        float pg = 0.0f, pg8 = 0.0f;
        #pragma unroll
        for (int np = 0; np < 16; np++) {
            float2 vv = *(const float2*)&V_s[np * 8 + 2 * c];
            pg  = fmaf(vv.x, tanhf(acc[np][0]), pg);
            pg  = fmaf(vv.y, tanhf(acc[np][1]), pg);
            pg8 = fmaf(vv.x, tanhf(acc[np][2]), pg8);
            pg8 = fmaf(vv.y, tanhf(acc[np][3]), pg8);
        }
        pg  += __shfl_xor_sync(0xFFFFFFFFu, pg, 1);
        pg  += __shfl_xor_sync(0xFFFFFFFFu, pg, 2);
        pg8 += __shfl_xor_sync(0xFFFFFFFFu, pg8, 1);
        pg8 += __shfl_xor_sync(0xFFFFFFFFu, pg8, 2);
        if (c == 0) {
            g_score[row0 + g] = pg;
            g_score[row0 + g + 8] = pg8;
        }
    }
}

// ================= K2: per-batch softmax stats =================
__global__ void softmax_stats_kernel() {
    const int b = blockIdx.x;
    const int tid = threadIdx.x;  // 256
    __shared__ float red[256];
    const float* s = g_score + b * PT;

    float m = -1e30f;
    for (int t = tid; t < PT; t += 256) m = fmaxf(m, s[t]);
    red[tid] = m;
    __syncthreads();
    for (int o = 128; o > 0; o >>= 1) {
        if (tid < o) red[tid] = fmaxf(red[tid], red[tid + o]);
        __syncthreads();
    }
    m = red[0];
    __syncthreads();

    float sum = 0.0f;
    for (int t = tid; t < PT; t += 256) sum += expf(s[t] - m);
    red[tid] = sum;
    __syncthreads();
    for (int o = 128; o > 0; o >>= 1) {
        if (tid < o) red[tid] += red[tid + o];
        __syncthreads();
    }
    if (tid == 0) { g_max[b] = m; g_rcp[b] = 1.0f / red[0]; }
}

// ================= K3: partial contexts (float4, 4-way t-split) =================
__global__ void context_partial_kernel(const float* __restrict__ enc) {
    const int cb = blockIdx.x, b = blockIdx.y;
    const int tid = threadIdx.x;          // 128
    const int d4 = tid & 31, tg = tid >> 5;
    __shared__ float wgt[TCHUNK];
    __shared__ float4 part[128];

    const float m = g_max[b], rcp = g_rcp[b];
    wgt[tid] = expf(g_score[b * PT + cb * TCHUNK + tid] - m) * rcp;
    __syncthreads();

    const float4* x = (const float4*)(enc + ((long)b * PT + cb * TCHUNK) * PD);
    float4 a = make_float4(0.f, 0.f, 0.f, 0.f);
    #pragma unroll 8
    for (int t = tg; t < TCHUNK; t += 4) {
        const float w = wgt[t];
        const float4 v = x[t * 32 + d4];
        a.x = fmaf(w, v.x, a.x); a.y = fmaf(w, v.y, a.y);
        a.z = fmaf(w, v.z, a.z); a.w = fmaf(w, v.w, a.w);
    }
    part[tid] = a;
    __syncthreads();
    if (tg == 0) {
        float4 p0 = part[d4], p1 = part[32 + d4], p2 = part[64 + d4], p3 = part[96 + d4];
        float4 r;
        r.x = (p0.x + p1.x) + (p2.x + p3.x);
        r.y = (p0.y + p1.y) + (p2.y + p3.y);
        r.z = (p0.z + p1.z) + (p2.z + p3.z);
        r.w = (p0.w + p1.w) + (p2.w + p3.w);
        ((float4*)(g_partial + (b * TCHUNKS + cb) * PD))[d4] = r;
    }
}

// ================= K4: deterministic final reduce =================
__global__ void context_reduce_kernel(float* __restrict__ out) {
    const int b = blockIdx.x, d = threadIdx.x;
    float acc = 0.0f;
    #pragma unroll
    for (int cc = 0; cc < TCHUNKS; cc++) acc += g_partial[(b * TCHUNKS + cc) * PD + d];
    out[b * PD + d] = acc;
}

// ================= launch =================
extern "C" void kernel_launch(void* const* d_in, const int* in_sizes, int n_in,
                              void* d_out, int out_size) {
    const float* enc = (const float*)d_in[0];
    const float* W1w = (const float*)d_in[1];
    const float* W1b = (const float*)d_in[2];
    const float* W2w = (const float*)d_in[3];
    const float* W2b = (const float*)d_in[4];
    const float* Vw  = (const float*)d_in[5];
    float* out = (float*)d_out;

    cudaFuncSetAttribute(score_kernel, cudaFuncAttributeMaxDynamicSharedMemorySize, K1_DSMEM);

    prep_kernel<<<64, 256>>>(W1w, W1b, W2w, W2b, Vw);
    score_kernel<<<SGRID, K1_THREADS, K1_DSMEM>>>(enc);
    softmax_stats_kernel<<<PB, 256>>>();
    dim3 g3(TCHUNKS, PB);
    context_partial_kernel<<<g3, TCHUNK>>>(enc);
    context_reduce_kernel<<<PB, PD>>>(out);
}

// round 5
// speedup vs baseline: 2.1425x; 1.0258x over previous
#include <cuda_runtime.h>
#include <cuda_bf16.h>
#include <math.h>
#include <stdint.h>

// Problem constants: B=64, T=2048, D=U=128
#define PB 64
#define PT 2048
#define PD 128
#define PU 128
#define NROWS (PB * PT)           // 131072
#define NWTILES (NROWS / 16)      // 8192 warp-tiles of 16 rows
#define SGRID 148
#define K1_WARPS 12
#define K1_THREADS (K1_WARPS * 32)
#define TOTAL_WARPS (SGRID * K1_WARPS)   // 1776
#define TCHUNKS 16
#define TCHUNK 128

// W smem: 128 rows x (256B data + 16B pad) per matrix
#define WPITCH 272
#define WBYTES (PD * WPITCH)      // 34816
#define K1_DSMEM (2 * WBYTES)     // 69632 bytes dynamic smem

// ---------------- device scratch ----------------
__device__ __align__(16) __nv_bfloat16 g_W_hi[PD * PU];  // (W1+W2) hi, [d][u]
__device__ __align__(16) __nv_bfloat16 g_W_lo[PD * PU];  // residual lo, [d][u]
__device__ float g_bias[PU];
__device__ float g_V[PU];
__device__ float g_score[NROWS];
__device__ float g_max[PB];
__device__ float g_rcp[PB];
__device__ __align__(16) float g_partial[PB * TCHUNKS * PD];

// ---------------- helpers ----------------
__device__ __forceinline__ uint32_t smem_u32(const void* p) {
    uint32_t a;
    asm("{ .reg .u64 t; cvta.to.shared.u64 t, %1; cvt.u32.u64 %0, t; }" : "=r"(a) : "l"(p));
    return a;
}
__device__ __forceinline__ uint32_t pack_bf(float a, float b) {
    __nv_bfloat162 t = __floats2bfloat162_rn(a, b);
    return *reinterpret_cast<uint32_t*>(&t);
}
// Exact-enough tanh: 1 - 2/(e^{2x}+1) via MUFU.EX2 + MUFU.RCP (~2^-22 rel err,
// correct saturation at +/-1). 5 instr vs ~30 for libdevice tanhf.
__device__ __forceinline__ float fast_tanh(float x) {
    float e, r;
    asm("ex2.approx.f32 %0, %1;" : "=f"(e) : "f"(x * 2.8853901817f)); // 2*log2(e)
    asm("rcp.approx.f32 %0, %1;" : "=f"(r) : "f"(e + 1.0f));
    return fmaf(-2.0f, r, 1.0f);
}
#define LDSM4T(r0, r1, r2, r3, addr) \
    asm volatile("ldmatrix.sync.aligned.m8n8.x4.trans.shared.b16 {%0,%1,%2,%3}, [%4];" \
                 : "=r"(r0), "=r"(r1), "=r"(r2), "=r"(r3) : "r"(addr))
#define MMA16816(d0, d1, d2, d3, a0, a1, a2, a3, b0, b1) \
    asm volatile("mma.sync.aligned.m16n8k16.row.col.f32.bf16.bf16.f32 " \
                 "{%0,%1,%2,%3}, {%4,%5,%6,%7}, {%8,%9}, {%0,%1,%2,%3};" \
                 : "+f"(d0), "+f"(d1), "+f"(d2), "+f"(d3) \
                 : "r"(a0), "r"(a1), "r"(a2), "r"(a3), "r"(b0), "r"(b1))

// ================= K0: fold + split weights (keeps [d][u] layout) =========
__global__ void prep_kernel(const float* __restrict__ W1w, const float* __restrict__ W1b,
                            const float* __restrict__ W2w, const float* __restrict__ W2b,
                            const float* __restrict__ Vw) {
    int i = blockIdx.x * blockDim.x + threadIdx.x;
    if (i < PD * PU) {
        float w = W1w[i] + W2w[i];
        __nv_bfloat16 hi = __float2bfloat16_rn(w);
        g_W_hi[i] = hi;
        g_W_lo[i] = __float2bfloat16_rn(w - __bfloat162float(hi));
    }
    if (i < PU) {
        g_bias[i] = W1b[i] + W2b[i];
        g_V[i] = Vw[i];               // V_b softmax-invariant, dropped
    }
}

// ================= K1: mma.sync score kernel =================
// s[row] = sum_u V[u] * tanh( (x @ W)[row,u] + bias[u] ), x@W via 3-term bf16 split.
// Warp-tile: 16 rows x 128 cols. A from gmem (register split), B (W) from smem
// via ldmatrix.x4.trans. acc: 16 n-chunks x 4 fp32 regs.
__global__ void __launch_bounds__(K1_THREADS, 1) score_kernel(const float* __restrict__ enc) {
    extern __shared__ __align__(16) char Wsm[];      // [0]=hi, [WBYTES]=lo (dynamic, 68KB)
    __shared__ float bias_s[PU], V_s[PU];

    const int tid = threadIdx.x, warp = tid >> 5, lane = tid & 31;
    const int g = lane >> 2, c = lane & 3;

    // stage W_hi/W_lo into padded smem (16B chunks)
    {
        const uint4* sh = (const uint4*)g_W_hi;
        const uint4* sl = (const uint4*)g_W_lo;
        for (int i = tid; i < PD * 16; i += K1_THREADS) {
            int row = i >> 4, ch = i & 15;
            *(uint4*)(Wsm + row * WPITCH + ch * 16) = sh[i];
            *(uint4*)(Wsm + WBYTES + row * WPITCH + ch * 16) = sl[i];
        }
        if (tid < PU) { bias_s[tid] = g_bias[tid]; V_s[tid] = g_V[tid]; }
    }
    __syncthreads();

    // per-lane ldmatrix base offset: mat0:(k+lr,n0) mat1:(k+8+lr,n0) mat2:(k+lr,n0+8) mat3:(k+8+lr,n0+8)
    const uint32_t lr = lane & 7, lg = lane >> 3;
    const uint32_t lds_off = (lr + ((lg & 1) << 3)) * WPITCH + ((lg >> 1) << 3) * 2;
    const uint32_t whi_a = smem_u32(Wsm) + lds_off;
    const uint32_t wlo_a = whi_a + WBYTES;

    const int gw = blockIdx.x * K1_WARPS + warp;

    for (int wt = gw; wt < NWTILES; wt += TOTAL_WARPS) {
        const long row0 = (long)wt * 16;
        const float* xr  = enc + (row0 + g) * PD + 2 * c;
        const float* xr8 = xr + 8 * PD;

        // init accumulators with bias (acc[np][0..1] and [2..3] share columns)
        float acc[16][4];
        #pragma unroll
        for (int np = 0; np < 16; np++) {
            float2 bb = *(const float2*)&bias_s[np * 8 + 2 * c];
            acc[np][0] = bb.x; acc[np][1] = bb.y;
            acc[np][2] = bb.x; acc[np][3] = bb.y;
        }

        #pragma unroll
        for (int k = 0; k < 8; k++) {
            // A fragment: load fp32, split to bf16 hi/lo in regs
            float2 p00 = *(const float2*)(xr  + k * 16);      // row g,   cols 2c..2c+1
            float2 p10 = *(const float2*)(xr8 + k * 16);      // row g+8
            float2 p01 = *(const float2*)(xr  + k * 16 + 8);  // row g,   cols 2c+8..
            float2 p11 = *(const float2*)(xr8 + k * 16 + 8);  // row g+8
            uint32_t Ah[4], Al[4];
            Ah[0] = pack_bf(p00.x, p00.y);
            Ah[1] = pack_bf(p10.x, p10.y);
            Ah[2] = pack_bf(p01.x, p01.y);
            Ah[3] = pack_bf(p11.x, p11.y);
            {
                __nv_bfloat162* h = (__nv_bfloat162*)Ah;
                float2 r0 = __bfloat1622float2(h[0]);
                float2 r1 = __bfloat1622float2(h[1]);
                float2 r2 = __bfloat1622float2(h[2]);
                float2 r3 = __bfloat1622float2(h[3]);
                Al[0] = pack_bf(p00.x - r0.x, p00.y - r0.y);
                Al[1] = pack_bf(p10.x - r1.x, p10.y - r1.y);
                Al[2] = pack_bf(p01.x - r2.x, p01.y - r2.y);
                Al[3] = pack_bf(p11.x - r3.x, p11.y - r3.y);
            }

            const uint32_t koff = (uint32_t)k * (16 * WPITCH);
            #pragma unroll
            for (int np2 = 0; np2 < 8; np2++) {
                uint32_t bh0, bh1, bh2, bh3, bl0, bl1, bl2, bl3;
                LDSM4T(bh0, bh1, bh2, bh3, whi_a + koff + np2 * 32);
                LDSM4T(bl0, bl1, bl2, bl3, wlo_a + koff + np2 * 32);
                float* a0 = acc[np2 * 2];
                float* a1 = acc[np2 * 2 + 1];
                MMA16816(a0[0], a0[1], a0[2], a0[3], Ah[0], Ah[1], Ah[2], Ah[3], bh0, bh1);
                MMA16816(a1[0], a1[1], a1[2], a1[3], Ah[0], Ah[1], Ah[2], Ah[3], bh2, bh3);
                MMA16816(a0[0], a0[1], a0[2], a0[3], Al[0], Al[1], Al[2], Al[3], bh0, bh1);
                MMA16816(a1[0], a1[1], a1[2], a1[3], Al[0], Al[1], Al[2], Al[3], bh2, bh3);
                MMA16816(a0[0], a0[1], a0[2], a0[3], Ah[0], Ah[1], Ah[2], Ah[3], bl0, bl1);
                MMA16816(a1[0], a1[1], a1[2], a1[3], Ah[0], Ah[1], Ah[2], Ah[3], bl2, bl3);
            }
        }

        // epilogue: tanh + V-dot, quad reduce, write 2 scores per quad-leader
        float pg = 0.0f, pg8 = 0.0f;
        #pragma unroll
        for (int np = 0; np < 16; np++) {
            float2 vv = *(const float2*)&V_s[np * 8 + 2 * c];
            pg  = fmaf(vv.x, fast_tanh(acc[np][0]), pg);
            pg  = fmaf(vv.y, fast_tanh(acc[np][1]), pg);
            pg8 = fmaf(vv.x, fast_tanh(acc[np][2]), pg8);
            pg8 = fmaf(vv.y, fast_tanh(acc[np][3]), pg8);
        }
        pg  += __shfl_xor_sync(0xFFFFFFFFu, pg, 1);
        pg  += __shfl_xor_sync(0xFFFFFFFFu, pg, 2);
        pg8 += __shfl_xor_sync(0xFFFFFFFFu, pg8, 1);
        pg8 += __shfl_xor_sync(0xFFFFFFFFu, pg8, 2);
        if (c == 0) {
            g_score[row0 + g] = pg;
            g_score[row0 + g + 8] = pg8;
        }
    }
}

// ================= K2: per-batch softmax stats =================
__global__ void softmax_stats_kernel() {
    const int b = blockIdx.x;
    const int tid = threadIdx.x;  // 256
    __shared__ float red[256];
    const float* s = g_score + b * PT;

    float m = -1e30f;
    for (int t = tid; t < PT; t += 256) m = fmaxf(m, s[t]);
    red[tid] = m;
    __syncthreads();
    for (int o = 128; o > 0; o >>= 1) {
        if (tid < o) red[tid] = fmaxf(red[tid], red[tid + o]);
        __syncthreads();
    }
    m = red[0];
    __syncthreads();

    float sum = 0.0f;
    for (int t = tid; t < PT; t += 256) sum += expf(s[t] - m);
    red[tid] = sum;
    __syncthreads();
    for (int o = 128; o > 0; o >>= 1) {
        if (tid < o) red[tid] += red[tid + o];
        __syncthreads();
    }
    if (tid == 0) { g_max[b] = m; g_rcp[b] = 1.0f / red[0]; }
}

// ================= K3: partial contexts (256 thr, 8 t-groups, float4) =====
__global__ void __launch_bounds__(256) context_partial_kernel(const float* __restrict__ enc) {
    const int cb = blockIdx.x, b = blockIdx.y;
    const int tid = threadIdx.x;          // 256
    const int d4 = tid & 31, tg = tid >> 5;   // 32 d-lanes x 8 t-groups
    __shared__ float wgt[TCHUNK];
    __shared__ float4 part[256];

    const float m = g_max[b], rcp = g_rcp[b];
    if (tid < TCHUNK)
        wgt[tid] = expf(g_score[b * PT + cb * TCHUNK + tid] - m) * rcp;
    __syncthreads();

    const float4* x = (const float4*)(enc + ((long)b * PT + cb * TCHUNK) * PD);
    float4 a = make_float4(0.f, 0.f, 0.f, 0.f);
    #pragma unroll
    for (int t = tg; t < TCHUNK; t += 8) {
        const float w = wgt[t];
        const float4 v = x[t * 32 + d4];
        a.x = fmaf(w, v.x, a.x); a.y = fmaf(w, v.y, a.y);
        a.z = fmaf(w, v.z, a.z); a.w = fmaf(w, v.w, a.w);
    }
    part[tid] = a;
    __syncthreads();
    if (tg == 0) {
        float4 r = make_float4(0.f, 0.f, 0.f, 0.f);
        #pragma unroll
        for (int j = 0; j < 8; j++) {
            float4 p = part[j * 32 + d4];
            r.x += p.x; r.y += p.y; r.z += p.z; r.w += p.w;
        }
        ((float4*)(g_partial + (b * TCHUNKS + cb) * PD))[d4] = r;
    }
}

// ================= K4: deterministic final reduce =================
__global__ void context_reduce_kernel(float* __restrict__ out) {
    const int b = blockIdx.x, d = threadIdx.x;
    float acc = 0.0f;
    #pragma unroll
    for (int cc = 0; cc < TCHUNKS; cc++) acc += g_partial[(b * TCHUNKS + cc) * PD + d];
    out[b * PD + d] = acc;
}

// ================= launch =================
extern "C" void kernel_launch(void* const* d_in, const int* in_sizes, int n_in,
                              void* d_out, int out_size) {
    const float* enc = (const float*)d_in[0];
    const float* W1w = (const float*)d_in[1];
    const float* W1b = (const float*)d_in[2];
    const float* W2w = (const float*)d_in[3];
    const float* W2b = (const float*)d_in[4];
    const float* Vw  = (const float*)d_in[5];
    float* out = (float*)d_out;

    cudaFuncSetAttribute(score_kernel, cudaFuncAttributeMaxDynamicSharedMemorySize, K1_DSMEM);

    prep_kernel<<<64, 256>>>(W1w, W1b, W2w, W2b, Vw);
    score_kernel<<<SGRID, K1_THREADS, K1_DSMEM>>>(enc);
    softmax_stats_kernel<<<PB, 256>>>();
    dim3 g3(TCHUNKS, PB);
    context_partial_kernel<<<g3, 256>>>(enc);
    context_reduce_kernel<<<PB, PD>>>(out);
}

// round 6
// speedup vs baseline: 2.4891x; 1.1618x over previous
#include <cuda_runtime.h>
#include <cuda_fp16.h>
#include <math.h>
#include <stdint.h>

// Problem constants: B=64, T=2048, D=U=128
#define PB 64
#define PT 2048
#define PD 128
#define PU 128
#define NROWS (PB * PT)           // 131072
#define NWTILES (NROWS / 16)      // 8192 warp-tiles of 16 rows
#define SGRID 148
#define K1_WARPS 12
#define K1_THREADS (K1_WARPS * 32)
#define TOTAL_WARPS (SGRID * K1_WARPS)   // 1776
#define TCHUNKS 16
#define TCHUNK 128

// W smem: 128 rows x (256B data + 16B pad)
#define WPITCH 272
#define WBYTES (PD * WPITCH)      // 34816 (static smem, fits 48KB)

// ---------------- device scratch ----------------
__device__ __align__(16) __half g_W_h[PD * PU];   // fp16(W1+W2), [d][u]
__device__ float g_bias[PU];
__device__ float g_V[PU];
__device__ float g_score[NROWS];
__device__ float g_max[PB];
__device__ float g_rcp[PB];
__device__ __align__(16) float g_partial[PB * TCHUNKS * PD];

// ---------------- helpers ----------------
__device__ __forceinline__ uint32_t smem_u32(const void* p) {
    uint32_t a;
    asm("{ .reg .u64 t; cvta.to.shared.u64 t, %1; cvt.u32.u64 %0, t; }" : "=r"(a) : "l"(p));
    return a;
}
// fp16 hi/lo split of a float pair: hi = fp16(x), lo = fp16(x - hi) (~22-bit x)
__device__ __forceinline__ void split_h2(float a, float b, uint32_t& hi, uint32_t& lo) {
    __half2 h = __floats2half2_rn(a, b);
    float2 r = __half22float2(h);
    __half2 l = __floats2half2_rn(a - r.x, b - r.y);
    hi = *reinterpret_cast<uint32_t*>(&h);
    lo = *reinterpret_cast<uint32_t*>(&l);
}
// Exact-enough tanh: 1 - 2/(e^{2x}+1) via MUFU.EX2 + MUFU.RCP
__device__ __forceinline__ float fast_tanh(float x) {
    float e, r;
    asm("ex2.approx.f32 %0, %1;" : "=f"(e) : "f"(x * 2.8853901817f)); // 2*log2(e)
    asm("rcp.approx.f32 %0, %1;" : "=f"(r) : "f"(e + 1.0f));
    return fmaf(-2.0f, r, 1.0f);
}
#define LDSM4T(r0, r1, r2, r3, addr) \
    asm volatile("ldmatrix.sync.aligned.m8n8.x4.trans.shared.b16 {%0,%1,%2,%3}, [%4];" \
                 : "=r"(r0), "=r"(r1), "=r"(r2), "=r"(r3) : "r"(addr))
#define MMA16816H(d0, d1, d2, d3, a0, a1, a2, a3, b0, b1) \
    asm volatile("mma.sync.aligned.m16n8k16.row.col.f32.f16.f16.f32 " \
                 "{%0,%1,%2,%3}, {%4,%5,%6,%7}, {%8,%9}, {%0,%1,%2,%3};" \
                 : "+f"(d0), "+f"(d1), "+f"(d2), "+f"(d3) \
                 : "r"(a0), "r"(a1), "r"(a2), "r"(a3), "r"(b0), "r"(b1))

// ================= K0: fold weights to fp16, [d][u] =================
__global__ void prep_kernel(const float* __restrict__ W1w, const float* __restrict__ W1b,
                            const float* __restrict__ W2w, const float* __restrict__ W2b,
                            const float* __restrict__ Vw) {
    int i = blockIdx.x * blockDim.x + threadIdx.x;
    if (i < PD * PU) g_W_h[i] = __float2half_rn(W1w[i] + W2w[i]);
    if (i < PU) {
        g_bias[i] = W1b[i] + W2b[i];
        g_V[i] = Vw[i];               // V_b softmax-invariant, dropped
    }
}

// ================= K1: mma.sync score kernel (fp16 2-pass) =================
// s[row] = sum_u V[u]*tanh((x@W)[row,u]+bias[u]); x split to fp16 hi/lo (2 passes
// sharing B fragments), W fp16 single. Warp-tile 16x128.
__global__ void __launch_bounds__(K1_THREADS, 1) score_kernel(const float* __restrict__ enc) {
    __shared__ __align__(16) char Wsm[WBYTES];
    __shared__ float bias_s[PU], V_s[PU];

    const int tid = threadIdx.x, warp = tid >> 5, lane = tid & 31;
    const int g = lane >> 2, c = lane & 3;

    // stage W into padded smem (16B chunks)
    {
        const uint4* sh = (const uint4*)g_W_h;
        for (int i = tid; i < PD * 16; i += K1_THREADS) {
            int row = i >> 4, ch = i & 15;
            *(uint4*)(Wsm + row * WPITCH + ch * 16) = sh[i];
        }
        if (tid < PU) { bias_s[tid] = g_bias[tid]; V_s[tid] = g_V[tid]; }
    }
    __syncthreads();

    // ldmatrix lane offset (verified mapping from round 4)
    const uint32_t lr = lane & 7, lg = lane >> 3;
    const uint32_t lds_off = (lr + ((lg & 1) << 3)) * WPITCH + ((lg >> 1) << 3) * 2;
    const uint32_t wh_a = smem_u32(Wsm) + lds_off;

    const int gw = blockIdx.x * K1_WARPS + warp;

    for (int wt = gw; wt < NWTILES; wt += TOTAL_WARPS) {
        const long row0 = (long)wt * 16;
        const float* xr  = enc + (row0 + g) * PD + 2 * c;
        const float* xr8 = xr + 8 * PD;

        float acc[16][4];
        #pragma unroll
        for (int np = 0; np < 16; np++) {
            float2 bb = *(const float2*)&bias_s[np * 8 + 2 * c];
            acc[np][0] = bb.x; acc[np][1] = bb.y;
            acc[np][2] = bb.x; acc[np][3] = bb.y;
        }

        #pragma unroll
        for (int k = 0; k < 8; k++) {
            float2 p00 = *(const float2*)(xr  + k * 16);
            float2 p10 = *(const float2*)(xr8 + k * 16);
            float2 p01 = *(const float2*)(xr  + k * 16 + 8);
            float2 p11 = *(const float2*)(xr8 + k * 16 + 8);
            uint32_t Ah[4], Al[4];
            split_h2(p00.x, p00.y, Ah[0], Al[0]);
            split_h2(p10.x, p10.y, Ah[1], Al[1]);
            split_h2(p01.x, p01.y, Ah[2], Al[2]);
            split_h2(p11.x, p11.y, Ah[3], Al[3]);

            const uint32_t koff = (uint32_t)k * (16 * WPITCH);
            #pragma unroll
            for (int np2 = 0; np2 < 8; np2++) {
                uint32_t b0, b1, b2, b3;
                LDSM4T(b0, b1, b2, b3, wh_a + koff + np2 * 32);
                float* a0 = acc[np2 * 2];
                float* a1 = acc[np2 * 2 + 1];
                MMA16816H(a0[0], a0[1], a0[2], a0[3], Ah[0], Ah[1], Ah[2], Ah[3], b0, b1);
                MMA16816H(a1[0], a1[1], a1[2], a1[3], Ah[0], Ah[1], Ah[2], Ah[3], b2, b3);
                MMA16816H(a0[0], a0[1], a0[2], a0[3], Al[0], Al[1], Al[2], Al[3], b0, b1);
                MMA16816H(a1[0], a1[1], a1[2], a1[3], Al[0], Al[1], Al[2], Al[3], b2, b3);
            }
        }

        // epilogue: tanh + V-dot, quad reduce
        float pg = 0.0f, pg8 = 0.0f;
        #pragma unroll
        for (int np = 0; np < 16; np++) {
            float2 vv = *(const float2*)&V_s[np * 8 + 2 * c];
            pg  = fmaf(vv.x, fast_tanh(acc[np][0]), pg);
            pg  = fmaf(vv.y, fast_tanh(acc[np][1]), pg);
            pg8 = fmaf(vv.x, fast_tanh(acc[np][2]), pg8);
            pg8 = fmaf(vv.y, fast_tanh(acc[np][3]), pg8);
        }
        pg  += __shfl_xor_sync(0xFFFFFFFFu, pg, 1);
        pg  += __shfl_xor_sync(0xFFFFFFFFu, pg, 2);
        pg8 += __shfl_xor_sync(0xFFFFFFFFu, pg8, 1);
        pg8 += __shfl_xor_sync(0xFFFFFFFFu, pg8, 2);
        if (c == 0) {
            g_score[row0 + g] = pg;
            g_score[row0 + g + 8] = pg8;
        }
    }
}

// ================= K2: per-batch softmax stats =================
__global__ void softmax_stats_kernel() {
    const int b = blockIdx.x;
    const int tid = threadIdx.x;  // 256
    __shared__ float red[256];
    const float* s = g_score + b * PT;

    float m = -1e30f;
    for (int t = tid; t < PT; t += 256) m = fmaxf(m, s[t]);
    red[tid] = m;
    __syncthreads();
    for (int o = 128; o > 0; o >>= 1) {
        if (tid < o) red[tid] = fmaxf(red[tid], red[tid + o]);
        __syncthreads();
    }
    m = red[0];
    __syncthreads();

    float sum = 0.0f;
    for (int t = tid; t < PT; t += 256) sum += expf(s[t] - m);
    red[tid] = sum;
    __syncthreads();
    for (int o = 128; o > 0; o >>= 1) {
        if (tid < o) red[tid] += red[tid + o];
        __syncthreads();
    }
    if (tid == 0) { g_max[b] = m; g_rcp[b] = 1.0f / red[0]; }
}

// ================= K3: partial contexts (256 thr, 8 t-groups, float4) =====
__global__ void __launch_bounds__(256) context_partial_kernel(const float* __restrict__ enc) {
    const int cb = blockIdx.x, b = blockIdx.y;
    const int tid = threadIdx.x;          // 256
    const int d4 = tid & 31, tg = tid >> 5;   // 32 d-lanes x 8 t-groups
    __shared__ float wgt[TCHUNK];
    __shared__ float4 part[256];

    const float m = g_max[b], rcp = g_rcp[b];
    if (tid < TCHUNK)
        wgt[tid] = expf(g_score[b * PT + cb * TCHUNK + tid] - m) * rcp;
    __syncthreads();

    const float4* x = (const float4*)(enc + ((long)b * PT + cb * TCHUNK) * PD);
    float4 a = make_float4(0.f, 0.f, 0.f, 0.f);
    #pragma unroll
    for (int t = tg; t < TCHUNK; t += 8) {
        const float w = wgt[t];
        const float4 v = x[t * 32 + d4];
        a.x = fmaf(w, v.x, a.x); a.y = fmaf(w, v.y, a.y);
        a.z = fmaf(w, v.z, a.z); a.w = fmaf(w, v.w, a.w);
    }
    part[tid] = a;
    __syncthreads();
    if (tg == 0) {
        float4 r = make_float4(0.f, 0.f, 0.f, 0.f);
        #pragma unroll
        for (int j = 0; j < 8; j++) {
            float4 p = part[j * 32 + d4];
            r.x += p.x; r.y += p.y; r.z += p.z; r.w += p.w;
        }
        ((float4*)(g_partial + (b * TCHUNKS + cb) * PD))[d4] = r;
    }
}

// ================= K4: deterministic final reduce =================
__global__ void context_reduce_kernel(float* __restrict__ out) {
    const int b = blockIdx.x, d = threadIdx.x;
    float acc = 0.0f;
    #pragma unroll
    for (int cc = 0; cc < TCHUNKS; cc++) acc += g_partial[(b * TCHUNKS + cc) * PD + d];
    out[b * PD + d] = acc;
}

// ================= launch =================
extern "C" void kernel_launch(void* const* d_in, const int* in_sizes, int n_in,
                              void* d_out, int out_size) {
    const float* enc = (const float*)d_in[0];
    const float* W1w = (const float*)d_in[1];
    const float* W1b = (const float*)d_in[2];
    const float* W2w = (const float*)d_in[3];
    const float* W2b = (const float*)d_in[4];
    const float* Vw  = (const float*)d_in[5];
    float* out = (float*)d_out;

    prep_kernel<<<64, 256>>>(W1w, W1b, W2w, W2b, Vw);
    score_kernel<<<SGRID, K1_THREADS>>>(enc);
    softmax_stats_kernel<<<PB, 256>>>();
    dim3 g3(TCHUNKS, PB);
    context_partial_kernel<<<g3, 256>>>(enc);
    context_reduce_kernel<<<PB, PD>>>(out);
}

// round 8
// speedup vs baseline: 3.0939x; 1.2430x over previous
#include <cuda_runtime.h>
#include <cuda_fp16.h>
#include <math.h>
#include <stdint.h>

// Problem constants: B=64, T=2048, D=U=128
#define PB 64
#define PT 2048
#define PD 128
#define PU 128
#define NROWS (PB * PT)           // 131072
#define NWTILES (NROWS / 16)      // 8192 warp-tiles of 16 rows
#define SGRID 148
#define K1_WARPS 12
#define K1_THREADS (K1_WARPS * 32)
#define TOTAL_WARPS (SGRID * K1_WARPS)   // 1776
#define TCHUNKS 16
#define TCHUNK 128

// W smem: 128 rows x (256B data + 16B pad)
#define WPITCH 272
#define WBYTES (PD * WPITCH)      // 34816 (static smem)

// ---------------- device scratch ----------------
__device__ float g_score[NROWS];
__device__ float g_max[PB];
__device__ float g_rcp[PB];
__device__ __align__(16) float g_partial[PB * TCHUNKS * PD];

// ---------------- helpers ----------------
__device__ __forceinline__ uint32_t smem_u32(const void* p) {
    uint32_t a;
    asm("{ .reg .u64 t; cvta.to.shared.u64 t, %1; cvt.u32.u64 %0, t; }" : "=r"(a) : "l"(p));
    return a;
}
__device__ __forceinline__ uint32_t pack_h2(float a, float b) {
    __half2 h = __floats2half2_rn(a, b);
    return *reinterpret_cast<uint32_t*>(&h);
}
// HW tanh: single MUFU.TANH op (sm_75+), abs err ~2^-10.6
__device__ __forceinline__ float hw_tanh(float x) {
    float y;
    asm("tanh.approx.f32 %0, %1;" : "=f"(y) : "f"(x));
    return y;
}
#define LDSM4T(r0, r1, r2, r3, addr) \
    asm volatile("ldmatrix.sync.aligned.m8n8.x4.trans.shared.b16 {%0,%1,%2,%3}, [%4];" \
                 : "=r"(r0), "=r"(r1), "=r"(r2), "=r"(r3) : "r"(addr))
#define MMA16816H(d0, d1, d2, d3, a0, a1, a2, a3, b0, b1) \
    asm volatile("mma.sync.aligned.m16n8k16.row.col.f32.f16.f16.f32 " \
                 "{%0,%1,%2,%3}, {%4,%5,%6,%7}, {%8,%9}, {%0,%1,%2,%3};" \
                 : "+f"(d0), "+f"(d1), "+f"(d2), "+f"(d3) \
                 : "r"(a0), "r"(a1), "r"(a2), "r"(a3), "r"(b0), "r"(b1))

// ================= K1: mma.sync score kernel (fp16 1-pass) =================
// s[row] = sum_u V[u]*tanh((x@W)[row,u]+bias[u]); x,W in fp16, fp32 accum.
// Warp-tile 16x128. W folded (W1+W2 -> fp16) in-kernel; no prep launch.
__global__ void __launch_bounds__(K1_THREADS, 1)
score_kernel(const float* __restrict__ enc,
             const float* __restrict__ W1w, const float* __restrict__ W1b,
             const float* __restrict__ W2w, const float* __restrict__ W2b,
             const float* __restrict__ Vw) {
    __shared__ __align__(16) char Wsm[WBYTES];
    __shared__ float bias_s[PU], V_s[PU];

    const int tid = threadIdx.x, warp = tid >> 5, lane = tid & 31;
    const int g = lane >> 2, c = lane & 3;

    // fold W1+W2 -> fp16 into padded smem (row=d, col=u); L2-hot after CTA 0
    for (int i = tid; i < PD * PU; i += K1_THREADS) {
        int d = i >> 7, u = i & 127;
        *(__half*)(Wsm + d * WPITCH + u * 2) = __float2half_rn(W1w[i] + W2w[i]);
    }
    if (tid < PU) {
        bias_s[tid] = W1b[tid] + W2b[tid];
        V_s[tid] = Vw[tid];               // V_b softmax-invariant, dropped
    }
    __syncthreads();

    // ldmatrix lane offset (verified mapping)
    const uint32_t lr = lane & 7, lg = lane >> 3;
    const uint32_t lds_off = (lr + ((lg & 1) << 3)) * WPITCH + ((lg >> 1) << 3) * 2;
    const uint32_t wh_a = smem_u32(Wsm) + lds_off;

    const int gw = blockIdx.x * K1_WARPS + warp;

    for (int wt = gw; wt < NWTILES; wt += TOTAL_WARPS) {
        const long row0 = (long)wt * 16;
        const float* xr  = enc + (row0 + g) * PD + 2 * c;
        const float* xr8 = xr + 8 * PD;

        float acc[16][4];
        #pragma unroll
        for (int np = 0; np < 16; np++) {
            float2 bb = *(const float2*)&bias_s[np * 8 + 2 * c];
            acc[np][0] = bb.x; acc[np][1] = bb.y;
            acc[np][2] = bb.x; acc[np][3] = bb.y;
        }

        #pragma unroll
        for (int k = 0; k < 8; k++) {
            float2 p00 = *(const float2*)(xr  + k * 16);
            float2 p10 = *(const float2*)(xr8 + k * 16);
            float2 p01 = *(const float2*)(xr  + k * 16 + 8);
            float2 p11 = *(const float2*)(xr8 + k * 16 + 8);
            uint32_t Ah[4];
            Ah[0] = pack_h2(p00.x, p00.y);
            Ah[1] = pack_h2(p10.x, p10.y);
            Ah[2] = pack_h2(p01.x, p01.y);
            Ah[3] = pack_h2(p11.x, p11.y);

            const uint32_t koff = (uint32_t)k * (16 * WPITCH);
            #pragma unroll
            for (int np2 = 0; np2 < 8; np2++) {
                uint32_t b0, b1, b2, b3;
                LDSM4T(b0, b1, b2, b3, wh_a + koff + np2 * 32);
                float* a0 = acc[np2 * 2];
                float* a1 = acc[np2 * 2 + 1];
                MMA16816H(a0[0], a0[1], a0[2], a0[3], Ah[0], Ah[1], Ah[2], Ah[3], b0, b1);
                MMA16816H(a1[0], a1[1], a1[2], a1[3], Ah[0], Ah[1], Ah[2], Ah[3], b2, b3);
            }
        }

        // epilogue: HW tanh + V-dot, quad reduce
        float pg = 0.0f, pg8 = 0.0f;
        #pragma unroll
        for (int np = 0; np < 16; np++) {
            float2 vv = *(const float2*)&V_s[np * 8 + 2 * c];
            pg  = fmaf(vv.x, hw_tanh(acc[np][0]), pg);
            pg  = fmaf(vv.y, hw_tanh(acc[np][1]), pg);
            pg8 = fmaf(vv.x, hw_tanh(acc[np][2]), pg8);
            pg8 = fmaf(vv.y, hw_tanh(acc[np][3]), pg8);
        }
        pg  += __shfl_xor_sync(0xFFFFFFFFu, pg, 1);
        pg  += __shfl_xor_sync(0xFFFFFFFFu, pg, 2);
        pg8 += __shfl_xor_sync(0xFFFFFFFFu, pg8, 1);
        pg8 += __shfl_xor_sync(0xFFFFFFFFu, pg8, 2);
        if (c == 0) {
            g_score[row0 + g] = pg;
            g_score[row0 + g + 8] = pg8;
        }
    }
}

// ================= K2: per-batch softmax stats =================
__global__ void softmax_stats_kernel() {
    const int b = blockIdx.x;
    const int tid = threadIdx.x;  // 256
    __shared__ float red[256];
    const float* s = g_score + b * PT;

    float m = -1e30f;
    for (int t = tid; t < PT; t += 256) m = fmaxf(m, s[t]);
    red[tid] = m;
    __syncthreads();
    for (int o = 128; o > 0; o >>= 1) {
        if (tid < o) red[tid] = fmaxf(red[tid], red[tid + o]);
        __syncthreads();
    }
    m = red[0];
    __syncthreads();

    float sum = 0.0f;
    for (int t = tid; t < PT; t += 256) sum += expf(s[t] - m);
    red[tid] = sum;
    __syncthreads();
    for (int o = 128; o > 0; o >>= 1) {
        if (tid < o) red[tid] += red[tid + o];
        __syncthreads();
    }
    if (tid == 0) { g_max[b] = m; g_rcp[b] = 1.0f / red[0]; }
}

// ================= K3: partial contexts (256 thr, 8 t-groups, float4) =====
__global__ void __launch_bounds__(256) context_partial_kernel(const float* __restrict__ enc) {
    const int cb = blockIdx.x, b = blockIdx.y;
    const int tid = threadIdx.x;          // 256
    const int d4 = tid & 31, tg = tid >> 5;   // 32 d-lanes x 8 t-groups
    __shared__ float wgt[TCHUNK];
    __shared__ float4 part[256];

    const float m = g_max[b], rcp = g_rcp[b];
    if (tid < TCHUNK)
        wgt[tid] = expf(g_score[b * PT + cb * TCHUNK + tid] - m) * rcp;
    __syncthreads();

    const float4* x = (const float4*)(enc + ((long)b * PT + cb * TCHUNK) * PD);
    float4 a = make_float4(0.f, 0.f, 0.f, 0.f);
    #pragma unroll
    for (int t = tg; t < TCHUNK; t += 8) {
        const float w = wgt[t];
        const float4 v = x[t * 32 + d4];
        a.x = fmaf(w, v.x, a.x); a.y = fmaf(w, v.y, a.y);
        a.z = fmaf(w, v.z, a.z); a.w = fmaf(w, v.w, a.w);
    }
    part[tid] = a;
    __syncthreads();
    if (tg == 0) {
        float4 r = make_float4(0.f, 0.f, 0.f, 0.f);
        #pragma unroll
        for (int j = 0; j < 8; j++) {
            float4 p = part[j * 32 + d4];
            r.x += p.x; r.y += p.y; r.z += p.z; r.w += p.w;
        }
        ((float4*)(g_partial + (b * TCHUNKS + cb) * PD))[d4] = r;
    }
}

// ================= K4: deterministic final reduce =================
__global__ void context_reduce_kernel(float* __restrict__ out) {
    const int b = blockIdx.x, d = threadIdx.x;
    float acc = 0.0f;
    #pragma unroll
    for (int cc = 0; cc < TCHUNKS; cc++) acc += g_partial[(b * TCHUNKS + cc) * PD + d];
    out[b * PD + d] = acc;
}

// ================= launch =================
extern "C" void kernel_launch(void* const* d_in, const int* in_sizes, int n_in,
                              void* d_out, int out_size) {
    const float* enc = (const float*)d_in[0];
    const float* W1w = (const float*)d_in[1];
    const float* W1b = (const float*)d_in[2];
    const float* W2w = (const float*)d_in[3];
    const float* W2b = (const float*)d_in[4];
    const float* Vw  = (const float*)d_in[5];
    float* out = (float*)d_out;

    score_kernel<<<SGRID, K1_THREADS>>>(enc, W1w, W1b, W2w, W2b, Vw);
    softmax_stats_kernel<<<PB, 256>>>();
    dim3 g3(TCHUNKS, PB);
    context_partial_kernel<<<g3, 256>>>(enc);
    context_reduce_kernel<<<PB, PD>>>(out);
}